// round 9
// baseline (speedup 1.0000x reference)
#include <cuda_runtime.h>
#include <cuda_fp16.h>
#include <math.h>

#define B_ROWS 4096
#define T_LEN  8192
#define SCAN_THREADS 1024
#define NWARPS (SCAN_THREADS / 32)     // 32
#define CHUNK (T_LEN / SCAN_THREADS)   // 8
#define GAMMA 0.99f
#define GAMMA8 0.9227446944279201f     // 0.99^8
#define EPS_N 1e-9f

// Scratch (device globals; no allocations allowed).
__device__ float    g_row_sum[B_ROWS];
__device__ float    g_row_inv[B_ROWS];
__device__ float    g_mean_val;
__device__ unsigned g_count;           // zero-init; atomicInc wraps -> self-reset per launch
// fp16 staging for unnormalized returns: 64 MB, L2-resident in steady state.
__device__ __align__(128) __half g_ret_h[(size_t)B_ROWS * T_LEN];

// ───────────────────────── scan: one block per row ─────────────────────────
// x_t = r_t + a_t * x_{t+1},  a_t = GAMMA*(1-done_t),  done in {0,1} exactly.
// 1024 threads × 8 elements: max occupancy (2 CTAs/SM = 64 warps), short chains.
__global__ __launch_bounds__(SCAN_THREADS, 2)
void scan_kernel(const float* __restrict__ rewards,
                 const float* __restrict__ dones)
{
    const int row  = blockIdx.x;
    const int tid  = threadIdx.x;
    const int lane = tid & 31;
    const int wid  = tid >> 5;
    const size_t row_off = (size_t)row * T_LEN;
    const int base = tid * CHUNK;

    float r[CHUNK];
    unsigned mask = 0;                 // bit t set -> done_t == 1 -> a_t == 0

    const float4* r4 = reinterpret_cast<const float4*>(rewards + row_off + base);
    const float4* d4 = reinterpret_cast<const float4*>(dones   + row_off + base);
#pragma unroll
    for (int i = 0; i < CHUNK / 4; i++) {
        float4 rv = __ldcs(r4 + i);
        float4 dv = __ldcs(d4 + i);
        r[i*4+0] = rv.x; r[i*4+1] = rv.y; r[i*4+2] = rv.z; r[i*4+3] = rv.w;
        mask |= (dv.x != 0.0f ? 1u : 0u) << (i*4+0);
        mask |= (dv.y != 0.0f ? 1u : 0u) << (i*4+1);
        mask |= (dv.z != 0.0f ? 1u : 0u) << (i*4+2);
        mask |= (dv.w != 0.0f ? 1u : 0u) << (i*4+3);
    }

    // Compose chunk into affine map (A, B): x_left = B + A * x_right.
    float A  = (mask == 0u) ? GAMMA8 : 0.0f;
    float Bc = 0.0f;
#pragma unroll
    for (int t = CHUNK - 1; t >= 0; t--) {
        float f = fmaf(GAMMA, Bc, r[t]);
        Bc = (mask & (1u << t)) ? r[t] : f;
    }

    // Warp-level inclusive SUFFIX scan via shuffles.
#pragma unroll
    for (int d = 1; d < 32; d <<= 1) {
        float A2 = __shfl_down_sync(0xFFFFFFFFu, A, d);
        float B2 = __shfl_down_sync(0xFFFFFFFFu, Bc, d);
        if (lane + d < 32) {
            Bc = fmaf(A, B2, Bc);
            A  = A * A2;
        }
    }

    __shared__ float sWA[NWARPS];
    __shared__ float sWB[NWARPS];
    __shared__ float sCB[NWARPS];
    if (lane == 0) { sWA[wid] = A; sWB[wid] = Bc; }
    __syncthreads();

    // Warp 0 scans the 32 warp aggregates (full warp, no guards).
    if (wid == 0) {
        float wA = sWA[lane];
        float wB = sWB[lane];
#pragma unroll
        for (int d = 1; d < 32; d <<= 1) {
            float A2 = __shfl_down_sync(0xFFFFFFFFu, wA, d);
            float B2 = __shfl_down_sync(0xFFFFFFFFu, wB, d);
            if (lane + d < 32) {
                wB = fmaf(wA, B2, wB);
                wA = wA * A2;
            }
        }
        float eB = __shfl_down_sync(0xFFFFFFFFu, wB, 1);
        if (lane == 31) eB = 0.0f;
        sCB[lane] = eB;
    }
    __syncthreads();

    float cB   = sCB[wid];
    float totB = fmaf(A, cB, Bc);
    float carry = __shfl_down_sync(0xFFFFFFFFu, totB, 1);
    if (lane == 31) carry = cB;        // last thread of block -> cB==0, correct

    // Replay chunk with true carry; values + row moments (f32 precision).
    float sum = 0.0f, sq = 0.0f;
#pragma unroll
    for (int t = CHUNK - 1; t >= 0; t--) {
        float f = fmaf(GAMMA, carry, r[t]);
        carry = (mask & (1u << t)) ? r[t] : f;
        r[t] = carry;
        sum += carry;
        sq = fmaf(carry, carry, sq);
    }

    // fp16 staging store: 8 halves = 16 bytes = one STG.128.
    __half2 h[CHUNK / 2];
#pragma unroll
    for (int i = 0; i < CHUNK / 2; i++)
        h[i] = __floats2half2_rn(r[2*i], r[2*i+1]);
    uint4* dst = reinterpret_cast<uint4*>(g_ret_h + row_off + base);
    dst[0] = *reinterpret_cast<const uint4*>(h);

    // Block reduction of (sum, sq).
#pragma unroll
    for (int d = 16; d > 0; d >>= 1) {
        sum += __shfl_down_sync(0xFFFFFFFFu, sum, d);
        sq  += __shfl_down_sync(0xFFFFFFFFu, sq,  d);
    }
    __shared__ float sS[NWARPS];
    __shared__ float sQ[NWARPS];
    if (lane == 0) { sS[wid] = sum; sQ[wid] = sq; }
    __syncthreads();
    if (tid < 32) {
        float ts = sS[lane];
        float tq = sQ[lane];
#pragma unroll
        for (int d = 16; d > 0; d >>= 1) {
            ts += __shfl_down_sync(0xFFFFFFFFu, ts, d);
            tq += __shfl_down_sync(0xFFFFFFFFu, tq, d);
        }
        if (lane == 0) {
            float mean = ts / (float)T_LEN;
            float var  = (tq - ts * mean) / (float)(T_LEN - 1);   // ddof=1
            g_row_sum[row] = ts;
            g_row_inv[row] = 1.0f / (sqrtf(fmaxf(var, 0.0f)) + EPS_N);
        }
    }

    // Last block to finish reduces the 4096 row sums -> global mean.
    __shared__ unsigned s_last;
    if (tid == 0) {
        __threadfence();
        unsigned prev = atomicInc(&g_count, B_ROWS - 1);   // wraps to 0: self-reset
        s_last = (prev == B_ROWS - 1) ? 1u : 0u;
    }
    __syncthreads();
    if (s_last) {
        float s = 0.0f;
#pragma unroll
        for (int i = 0; i < B_ROWS / SCAN_THREADS; i++)
            s += __ldcg(&g_row_sum[tid + i * SCAN_THREADS]);
#pragma unroll
        for (int d = 16; d > 0; d >>= 1)
            s += __shfl_down_sync(0xFFFFFFFFu, s, d);
        if (lane == 0) sS[wid] = s;
        __syncthreads();
        if (tid < 32) {
            float t = sS[lane];
#pragma unroll
            for (int d = 16; d > 0; d >>= 1)
                t += __shfl_down_sync(0xFFFFFFFFu, t, d);
            if (tid == 0)
                g_mean_val = t / ((float)B_ROWS * (float)T_LEN);
        }
    }
}

// ── normalize: read fp16 staging (L2-resident, LAST-USE), write f32 (streaming) ──
// R8-proven config — unchanged: 512 threads, 16 elements/thread (2 uint4 loads).
#define NORM_ELEMS 16
__global__ __launch_bounds__(512)
void norm_kernel(float* __restrict__ out)
{
    const float gmean = g_mean_val;
    const int i = blockIdx.x * blockDim.x + threadIdx.x;
    const size_t base = (size_t)i * NORM_ELEMS;
    const int row = (int)(base >> 13);           // / T_LEN
    const float inv = g_row_inv[row];
    const float neg = -gmean * inv;

    const uint4* src = reinterpret_cast<const uint4*>(g_ret_h + base);
    uint4 u0 = __ldlu(src + 0);
    uint4 u1 = __ldlu(src + 1);

    const __half2* h0 = reinterpret_cast<const __half2*>(&u0);
    const __half2* h1 = reinterpret_cast<const __half2*>(&u1);

    float4* o4 = reinterpret_cast<float4*>(out + base);
    float4 v;
#pragma unroll
    for (int j = 0; j < 2; j++) {
        float2 a = __half22float2(h0[2*j+0]);
        float2 b = __half22float2(h0[2*j+1]);
        v.x = fmaf(a.x, inv, neg); v.y = fmaf(a.y, inv, neg);
        v.z = fmaf(b.x, inv, neg); v.w = fmaf(b.y, inv, neg);
        __stcs(o4 + j, v);
    }
#pragma unroll
    for (int j = 0; j < 2; j++) {
        float2 a = __half22float2(h1[2*j+0]);
        float2 b = __half22float2(h1[2*j+1]);
        v.x = fmaf(a.x, inv, neg); v.y = fmaf(a.y, inv, neg);
        v.z = fmaf(b.x, inv, neg); v.w = fmaf(b.y, inv, neg);
        __stcs(o4 + 2 + j, v);
    }
}

extern "C" void kernel_launch(void* const* d_in, const int* in_sizes, int n_in,
                              void* d_out, int out_size)
{
    const float* rewards = (const float*)d_in[0];
    const float* dones   = (const float*)d_in[1];
    float* out = (float*)d_out;

    scan_kernel<<<B_ROWS, SCAN_THREADS>>>(rewards, dones);
    const int nthreads = B_ROWS * (T_LEN / NORM_ELEMS);   // 2M
    norm_kernel<<<nthreads / 512, 512>>>(out);
}

// round 10
// speedup vs baseline: 1.1714x; 1.1714x over previous
#include <cuda_runtime.h>
#include <cuda_fp16.h>
#include <math.h>

#define B_ROWS 4096
#define T_LEN  8192
#define SCAN_THREADS 512
#define NWARPS (SCAN_THREADS / 32)     // 16
#define CHUNK (T_LEN / SCAN_THREADS)   // 16
#define GROUPS (T_LEN / 4)             // 2048 float4-groups per row
#define GAMMA 0.99f
#define GAMMA16 0.8514577710948755f    // 0.99^16
#define EPS_N 1e-9f
#define RPAD 513                       // padded row stride (words) for transpose smem

// Scratch (device globals; no allocations allowed).
__device__ float    g_row_sum[B_ROWS];
__device__ float    g_row_inv[B_ROWS];
__device__ float    g_mean_val;
__device__ unsigned g_count;           // zero-init; atomicInc wraps -> self-reset per launch
// fp16 staging for unnormalized returns: 64 MB, L2-resident in steady state.
__device__ __align__(128) __half g_ret_h[(size_t)B_ROWS * T_LEN];

// ───────────────────────── scan: one block per row ─────────────────────────
// x_t = r_t + a_t * x_{t+1},  a_t = GAMMA*(1-done_t),  done in {0,1} exactly.
// All GMEM traffic fully coalesced; ownership transpose happens in smem.
// Element e lives at s_rew[(e%16)*RPAD + e/16]  (owner tid = e/16, t = e%16).
__global__ __launch_bounds__(SCAN_THREADS, 3)
void scan_kernel(const float* __restrict__ rewards,
                 const float* __restrict__ dones)
{
    const int row  = blockIdx.x;
    const int tid  = threadIdx.x;
    const int lane = tid & 31;
    const int wid  = tid >> 5;
    const size_t row_off = (size_t)row * T_LEN;

    __shared__ float    s_rew[16 * RPAD];   // transposed rewards (and later results)
    __shared__ unsigned s_db[GROUPS];       // 4 done-bytes packed per word (group g)
    __shared__ float    sWA[NWARPS], sWB[NWARPS], sCB[NWARPS];
    __shared__ float    sS[NWARPS],  sQ[NWARPS];
    __shared__ unsigned s_last;

    // ── Phase 1: coalesced load (lane-contiguous float4 groups) -> smem ──
    const float4* r4 = reinterpret_cast<const float4*>(rewards + row_off);
    const float4* d4 = reinterpret_cast<const float4*>(dones   + row_off);
#pragma unroll
    for (int k = 0; k < 4; k++) {
        const int g = tid + 512 * k;              // group id, lanes contiguous
        float4 rv = __ldcs(r4 + g);
        float4 dv = __ldcs(d4 + g);
        const int c = (g & 3) * 4;                // element-within-16 base
        const int q = g >> 2;                     // owner-tid coordinate
        s_rew[(c + 0) * RPAD + q] = rv.x;
        s_rew[(c + 1) * RPAD + q] = rv.y;
        s_rew[(c + 2) * RPAD + q] = rv.z;
        s_rew[(c + 3) * RPAD + q] = rv.w;
        unsigned p = (dv.x != 0.0f ? 1u : 0u)
                   | (dv.y != 0.0f ? 1u : 0u) << 8
                   | (dv.z != 0.0f ? 1u : 0u) << 16
                   | (dv.w != 0.0f ? 1u : 0u) << 24;
        s_db[g] = p;
    }
    __syncthreads();

    // ── Phase 2: owner gathers its 16 time-contiguous elements ──
    float r[CHUNK];
#pragma unroll
    for (int t = 0; t < CHUNK; t++)
        r[t] = s_rew[t * RPAD + tid];             // lanes contiguous: conflict-free

    unsigned mask = 0;
    {
        const uint4 dw = *reinterpret_cast<const uint4*>(&s_db[tid * 4]);
        const unsigned w[4] = {dw.x, dw.y, dw.z, dw.w};
#pragma unroll
        for (int q = 0; q < 4; q++) {
            mask |= ((w[q] >> 0)  & 1u) << (4*q + 0);
            mask |= ((w[q] >> 8)  & 1u) << (4*q + 1);
            mask |= ((w[q] >> 16) & 1u) << (4*q + 2);
            mask |= ((w[q] >> 24) & 1u) << (4*q + 3);
        }
    }

    // Compose chunk into affine map (A, B): x_left = B + A * x_right.
    float A  = (mask == 0u) ? GAMMA16 : 0.0f;
    float Bc = 0.0f;
#pragma unroll
    for (int t = CHUNK - 1; t >= 0; t--) {
        float f = fmaf(GAMMA, Bc, r[t]);
        Bc = (mask & (1u << t)) ? r[t] : f;
    }

    // Warp-level inclusive SUFFIX scan via shuffles.
#pragma unroll
    for (int d = 1; d < 32; d <<= 1) {
        float A2 = __shfl_down_sync(0xFFFFFFFFu, A, d);
        float B2 = __shfl_down_sync(0xFFFFFFFFu, Bc, d);
        if (lane + d < 32) {
            Bc = fmaf(A, B2, Bc);
            A  = A * A2;
        }
    }

    if (lane == 0) { sWA[wid] = A; sWB[wid] = Bc; }
    __syncthreads();

    if (wid == 0) {
        float wA = (lane < NWARPS) ? sWA[lane] : 1.0f;
        float wB = (lane < NWARPS) ? sWB[lane] : 0.0f;
#pragma unroll
        for (int d = 1; d < NWARPS; d <<= 1) {
            float A2 = __shfl_down_sync(0xFFFFFFFFu, wA, d);
            float B2 = __shfl_down_sync(0xFFFFFFFFu, wB, d);
            if (lane + d < NWARPS) {
                wB = fmaf(wA, B2, wB);
                wA = wA * A2;
            }
        }
        float eB = __shfl_down_sync(0xFFFFFFFFu, wB, 1);
        if (lane == NWARPS - 1) eB = 0.0f;
        if (lane < NWARPS) sCB[lane] = eB;
    }
    __syncthreads();

    float cB   = sCB[wid];
    float totB = fmaf(A, cB, Bc);
    float carry = __shfl_down_sync(0xFFFFFFFFu, totB, 1);
    if (lane == 31) carry = cB;        // tid==511 -> cB==0, correct

    // ── Phase 3: replay with true carry; moments + transposed writeback ──
    float sum = 0.0f, sq = 0.0f;
#pragma unroll
    for (int t = CHUNK - 1; t >= 0; t--) {
        float f = fmaf(GAMMA, carry, r[t]);
        carry = (mask & (1u << t)) ? r[t] : f;
        r[t] = carry;
        sum += carry;
        sq = fmaf(carry, carry, sq);
    }
    // Safe to overwrite s_rew: every thread passed Phase-2 reads at the first barrier.
#pragma unroll
    for (int t = 0; t < CHUNK; t++)
        s_rew[t * RPAD + tid] = r[t];

    // Block reduction of (sum, sq) (overlaps with smem writeback draining).
#pragma unroll
    for (int d = 16; d > 0; d >>= 1) {
        sum += __shfl_down_sync(0xFFFFFFFFu, sum, d);
        sq  += __shfl_down_sync(0xFFFFFFFFu, sq,  d);
    }
    if (lane == 0) { sS[wid] = sum; sQ[wid] = sq; }
    __syncthreads();
    if (tid < 32) {
        float ts = (lane < NWARPS) ? sS[lane] : 0.0f;
        float tq = (lane < NWARPS) ? sQ[lane] : 0.0f;
#pragma unroll
        for (int d = NWARPS / 2; d > 0; d >>= 1) {
            ts += __shfl_down_sync(0xFFFFFFFFu, ts, d);
            tq += __shfl_down_sync(0xFFFFFFFFu, tq, d);
        }
        if (lane == 0) {
            float mean = ts / (float)T_LEN;
            float var  = (tq - ts * mean) / (float)(T_LEN - 1);   // ddof=1
            g_row_sum[row] = ts;
            g_row_inv[row] = 1.0f / (sqrtf(fmaxf(var, 0.0f)) + EPS_N);
        }
    }
    // (the barrier above also orders the s_rew writeback for Phase 4)

    // ── Phase 4: coalesced fp16 staging store (lane-contiguous 8B units) ──
    uint2* stg = reinterpret_cast<uint2*>(g_ret_h + row_off);
#pragma unroll
    for (int k = 0; k < 4; k++) {
        const int g = tid + 512 * k;
        const int c = (g & 3) * 4;
        const int q = g >> 2;
        float v0 = s_rew[(c + 0) * RPAD + q];
        float v1 = s_rew[(c + 1) * RPAD + q];
        float v2 = s_rew[(c + 2) * RPAD + q];
        float v3 = s_rew[(c + 3) * RPAD + q];
        __half2 h0 = __floats2half2_rn(v0, v1);
        __half2 h1 = __floats2half2_rn(v2, v3);
        uint2 u;
        u.x = *reinterpret_cast<unsigned*>(&h0);
        u.y = *reinterpret_cast<unsigned*>(&h1);
        stg[g] = u;
    }

    // Last block to finish reduces the 4096 row sums -> global mean.
    if (tid == 0) {
        __threadfence();
        unsigned prev = atomicInc(&g_count, B_ROWS - 1);   // wraps to 0: self-reset
        s_last = (prev == B_ROWS - 1) ? 1u : 0u;
    }
    __syncthreads();
    if (s_last) {
        float s = 0.0f;
#pragma unroll
        for (int i = 0; i < B_ROWS / SCAN_THREADS; i++)
            s += __ldcg(&g_row_sum[tid + i * SCAN_THREADS]);
#pragma unroll
        for (int d = 16; d > 0; d >>= 1)
            s += __shfl_down_sync(0xFFFFFFFFu, s, d);
        if (lane == 0) sS[wid] = s;
        __syncthreads();
        if (tid < 32) {
            float t = (lane < NWARPS) ? sS[lane] : 0.0f;
#pragma unroll
            for (int d = 16; d > 0; d >>= 1)
                t += __shfl_down_sync(0xFFFFFFFFu, t, d);
            if (tid == 0)
                g_mean_val = t / ((float)B_ROWS * (float)T_LEN);
        }
    }
}

// ── normalize: fully coalesced. One block per row; unit = 4 elements. ──
// Thread processes units u = tid + 512k (lane-contiguous): LDG.64 staging
// (last-use), STG.128 output (streaming). MLP=4 front-batched loads.
__global__ __launch_bounds__(512)
void norm_kernel(float* __restrict__ out)
{
    const int row = blockIdx.x;
    const float inv = g_row_inv[row];
    const float neg = -g_mean_val * inv;
    const size_t unit0 = (size_t)row * GROUPS + threadIdx.x;

    const uint2* src = reinterpret_cast<const uint2*>(g_ret_h);
    float4* o4 = reinterpret_cast<float4*>(out);

    uint2 p[4];
#pragma unroll
    for (int k = 0; k < 4; k++)
        p[k] = __ldlu(src + unit0 + 512 * k);     // front-batched, coalesced

#pragma unroll
    for (int k = 0; k < 4; k++) {
        __half2 h0 = *reinterpret_cast<__half2*>(&p[k].x);
        __half2 h1 = *reinterpret_cast<__half2*>(&p[k].y);
        float2 a = __half22float2(h0);
        float2 b = __half22float2(h1);
        float4 v;
        v.x = fmaf(a.x, inv, neg);
        v.y = fmaf(a.y, inv, neg);
        v.z = fmaf(b.x, inv, neg);
        v.w = fmaf(b.y, inv, neg);
        __stcs(o4 + unit0 + 512 * k, v);
    }
}

extern "C" void kernel_launch(void* const* d_in, const int* in_sizes, int n_in,
                              void* d_out, int out_size)
{
    const float* rewards = (const float*)d_in[0];
    const float* dones   = (const float*)d_in[1];
    float* out = (float*)d_out;

    scan_kernel<<<B_ROWS, SCAN_THREADS>>>(rewards, dones);
    norm_kernel<<<B_ROWS, 512>>>(out);
}